// round 1
// baseline (speedup 1.0000x reference)
#include <cuda_runtime.h>

// Problem constants
#define B_   32
#define K_   3
#define N_   512
#define FIN  64
#define FOUT 64
#define T_   64
#define R_   (K_ * N_)       // 1536  combined (k,m) reduction dim
#define C_   (FOUT * T_)     // 4096  combined (o,t) column dim

// Scratch (global-memory-resident, allocated at module load; no runtime allocs)
__device__ float g_A2[(size_t)B_ * N_ * R_];   // [b][n][k*512+m]  ~100.7 MB
__device__ float g_Z2[(size_t)B_ * R_ * C_];   // [b][k*512+m][o*64+t]  ~805 MB

// ---------------------------------------------------------------------------
// packed f32x2 helpers (SASS FFMA2 — double-rate fp32 FMA, only via PTX)
// ---------------------------------------------------------------------------
union U64 {
    unsigned long long u;
    float2 f;
};

__device__ __forceinline__ void fma2(unsigned long long& d,
                                     unsigned long long a,
                                     unsigned long long b) {
    asm("fma.rn.f32x2 %0, %1, %2, %3;" : "=l"(d) : "l"(a), "l"(b), "l"(d));
}

// ---------------------------------------------------------------------------
// Kernel 1: A2[b][n][k*512+m] = cheb[k,n,m] * softmax_m(scores[b,k,n,m]
//                                                       + adj[n,m]*mask[k,n,m])
// One block (128 threads) per row of 512; float4 per thread.
// ---------------------------------------------------------------------------
__global__ void __launch_bounds__(128) k_softmax_aeff(
    const float* __restrict__ scores,
    const float* __restrict__ adj,
    const float* __restrict__ mask,
    const float* __restrict__ cheb)
{
    const int n = blockIdx.x, k = blockIdx.y, b = blockIdx.z;
    const int tid  = threadIdx.x;
    const int lane = tid & 31, wid = tid >> 5;

    const float4* srow = (const float4*)(scores + (((size_t)(b * K_ + k) * N_ + n) * N_));
    const float4* arow = (const float4*)(adj    + (size_t)n * N_);
    const float4* mrow = (const float4*)(mask   + ((size_t)(k * N_ + n) * N_));
    const float4* crow = (const float4*)(cheb   + ((size_t)(k * N_ + n) * N_));

    float4 s = srow[tid], a = arow[tid], mk = mrow[tid];
    float v0 = s.x + a.x * mk.x;
    float v1 = s.y + a.y * mk.y;
    float v2 = s.z + a.z * mk.z;
    float v3 = s.w + a.w * mk.w;

    // row max
    float mx = fmaxf(fmaxf(v0, v1), fmaxf(v2, v3));
    #pragma unroll
    for (int o = 16; o; o >>= 1) mx = fmaxf(mx, __shfl_xor_sync(0xffffffffu, mx, o));
    __shared__ float rmax[4], rsum[4];
    if (lane == 0) rmax[wid] = mx;
    __syncthreads();
    mx = fmaxf(fmaxf(rmax[0], rmax[1]), fmaxf(rmax[2], rmax[3]));

    float e0 = __expf(v0 - mx);
    float e1 = __expf(v1 - mx);
    float e2 = __expf(v2 - mx);
    float e3 = __expf(v3 - mx);

    // row sum
    float sm = (e0 + e1) + (e2 + e3);
    #pragma unroll
    for (int o = 16; o; o >>= 1) sm += __shfl_xor_sync(0xffffffffu, sm, o);
    if (lane == 0) rsum[wid] = sm;
    __syncthreads();
    sm = (rsum[0] + rsum[1]) + (rsum[2] + rsum[3]);
    float inv = 1.0f / sm;

    float4 c = crow[tid];
    float4 o4;
    o4.x = c.x * (e0 * inv);
    o4.y = c.y * (e1 * inv);
    o4.z = c.z * (e2 * inv);
    o4.w = c.w * (e3 * inv);

    float4* dst = (float4*)(g_A2 + (((size_t)(b * N_ + n) * K_ + k) * N_));
    dst[tid] = o4;
}

// ---------------------------------------------------------------------------
// Kernel 2: z[b][k*512+m][o*64+t] = sum_i x[b,m,i,t] * Theta[k,i,o]
// One block (256 threads) per (b,k,m); 64x64x64 GEMM in shared memory.
// Thread (ty,tx): 4 o's x 4 t's micro-tile, f32x2 accumulation over t-pairs.
// ---------------------------------------------------------------------------
__global__ void __launch_bounds__(256) k_xtheta(
    const float* __restrict__ x,
    const float* __restrict__ Theta)
{
    const int m = blockIdx.x, k = blockIdx.y, b = blockIdx.z;
    const int tid = threadIdx.x;

    __shared__ float Xs[FIN * T_];     // [i][t]
    __shared__ float Th[FIN * FOUT];   // [i][o]

    const float4* xg = (const float4*)(x + ((size_t)(b * N_ + m) * (FIN * T_)));
    const float4* tg = (const float4*)(Theta + (size_t)k * FIN * FOUT);
    float4* Xs4 = (float4*)Xs;
    float4* Th4 = (float4*)Th;
    #pragma unroll
    for (int j = 0; j < 4; j++) {
        Xs4[tid + j * 256] = xg[tid + j * 256];
        Th4[tid + j * 256] = tg[tid + j * 256];
    }
    __syncthreads();

    const int tx = tid & 15;   // t quad: t = tx*4 .. tx*4+3
    const int ty = tid >> 4;   // o quad: o = ty*4 .. ty*4+3

    U64 acc[4][2];
    #pragma unroll
    for (int oj = 0; oj < 4; oj++) { acc[oj][0].u = 0ull; acc[oj][1].u = 0ull; }

    #pragma unroll 8
    for (int i = 0; i < FIN; i++) {
        float4 xv = Xs4[i * 16 + tx];
        float4 tv = Th4[i * 16 + ty];
        U64 xp0; xp0.f = make_float2(xv.x, xv.y);
        U64 xp1; xp1.f = make_float2(xv.z, xv.w);
        float to[4] = {tv.x, tv.y, tv.z, tv.w};
        #pragma unroll
        for (int oj = 0; oj < 4; oj++) {
            U64 ad; ad.f = make_float2(to[oj], to[oj]);
            fma2(acc[oj][0].u, ad.u, xp0.u);
            fma2(acc[oj][1].u, ad.u, xp1.u);
        }
    }

    float* zb = g_Z2 + ((size_t)(b * R_ + k * N_ + m) * C_);
    #pragma unroll
    for (int oj = 0; oj < 4; oj++) {
        float4 v;
        v.x = acc[oj][0].f.x; v.y = acc[oj][0].f.y;
        v.z = acc[oj][1].f.x; v.w = acc[oj][1].f.y;
        *(float4*)(zb + (ty * 4 + oj) * T_ + tx * 4) = v;
    }
}

// ---------------------------------------------------------------------------
// Kernel 3: per batch b: out[b] = relu(A2[b] (512x1536) @ Z2[b] (1536x4096))
// Tile 128x128, Ktile 8, 256 threads, 8x8 micro-tile, f32x2 accumulators.
// ---------------------------------------------------------------------------
__global__ void __launch_bounds__(256, 2) k_gemm(float* __restrict__ out)
{
    const int nt = blockIdx.x, mt = blockIdx.y, b = blockIdx.z;

    __shared__ float As[8][128];   // transposed: [k][m]
    __shared__ float Bs[8][128];   // [k][n]

    const float* Ab = g_A2 + (size_t)b * N_ * R_ + (size_t)mt * 128 * R_;
    const float* Bb = g_Z2 + (size_t)b * R_ * C_ + (size_t)nt * 128;

    const int tid  = threadIdx.x;
    const int arow = tid >> 1, akq = tid & 1;          // A loader: 128 rows x 2 quads
    const int brow = tid >> 5, bcol = (tid & 31) * 4;  // B loader: 8 rows x 128 cols
    const int tx = tid & 15, ty = tid >> 4;            // micro-tile coords

    U64 acc[8][4];
    #pragma unroll
    for (int mi = 0; mi < 8; mi++)
        #pragma unroll
        for (int np = 0; np < 4; np++) acc[mi][np].u = 0ull;

    for (int kt = 0; kt < R_; kt += 8) {
        float4 av = *(const float4*)(Ab + (size_t)arow * R_ + kt + akq * 4);
        float4 bv = *(const float4*)(Bb + (size_t)(kt + brow) * C_ + bcol);
        __syncthreads();
        As[akq * 4 + 0][arow] = av.x;
        As[akq * 4 + 1][arow] = av.y;
        As[akq * 4 + 2][arow] = av.z;
        As[akq * 4 + 3][arow] = av.w;
        *(float4*)&Bs[brow][bcol] = bv;
        __syncthreads();

        #pragma unroll
        for (int kk = 0; kk < 8; kk++) {
            float4 a0 = *(const float4*)&As[kk][ty * 4];
            float4 a1 = *(const float4*)&As[kk][64 + ty * 4];
            float4 b0 = *(const float4*)&Bs[kk][tx * 4];
            float4 b1 = *(const float4*)&Bs[kk][64 + tx * 4];
            U64 bp[4];
            bp[0].f = make_float2(b0.x, b0.y);
            bp[1].f = make_float2(b0.z, b0.w);
            bp[2].f = make_float2(b1.x, b1.y);
            bp[3].f = make_float2(b1.z, b1.w);
            float am[8] = {a0.x, a0.y, a0.z, a0.w, a1.x, a1.y, a1.z, a1.w};
            #pragma unroll
            for (int mi = 0; mi < 8; mi++) {
                U64 ad; ad.f = make_float2(am[mi], am[mi]);
                #pragma unroll
                for (int np = 0; np < 4; np++) fma2(acc[mi][np].u, ad.u, bp[np].u);
            }
        }
    }

    float* Cb = out + (size_t)b * N_ * C_ + (size_t)(mt * 128) * C_ + (size_t)nt * 128;
    #pragma unroll
    for (int mi = 0; mi < 8; mi++) {
        int ml = (mi < 4) ? (ty * 4 + mi) : (64 + ty * 4 + (mi - 4));
        float4 v0, v1;
        v0.x = fmaxf(acc[mi][0].f.x, 0.f); v0.y = fmaxf(acc[mi][0].f.y, 0.f);
        v0.z = fmaxf(acc[mi][1].f.x, 0.f); v0.w = fmaxf(acc[mi][1].f.y, 0.f);
        v1.x = fmaxf(acc[mi][2].f.x, 0.f); v1.y = fmaxf(acc[mi][2].f.y, 0.f);
        v1.z = fmaxf(acc[mi][3].f.x, 0.f); v1.w = fmaxf(acc[mi][3].f.y, 0.f);
        *(float4*)(Cb + (size_t)ml * C_ + tx * 4)      = v0;
        *(float4*)(Cb + (size_t)ml * C_ + 64 + tx * 4) = v1;
    }
}

// ---------------------------------------------------------------------------
// Launch
// ---------------------------------------------------------------------------
extern "C" void kernel_launch(void* const* d_in, const int* in_sizes, int n_in,
                              void* d_out, int out_size) {
    (void)in_sizes; (void)n_in; (void)out_size;
    const float* x      = (const float*)d_in[0];  // [B,N,FIN,T]
    const float* scores = (const float*)d_in[1];  // [B,K,N,N]
    const float* adj    = (const float*)d_in[2];  // [N,N]
    const float* cheb   = (const float*)d_in[3];  // [K,N,N]
    const float* Theta  = (const float*)d_in[4];  // [K,FIN,FOUT]
    const float* mask   = (const float*)d_in[5];  // [K,N,N]
    float* out = (float*)d_out;                   // [B,N,FOUT,T]

    dim3 g1(N_, K_, B_);
    k_softmax_aeff<<<g1, 128>>>(scores, adj, mask, cheb);

    dim3 g2(N_, K_, B_);
    k_xtheta<<<g2, 256>>>(x, Theta);

    dim3 g3(C_ / 128, N_ / 128, B_);
    k_gemm<<<g3, 256>>>(out);
}

// round 3
// speedup vs baseline: 2.9864x; 2.9864x over previous
#include <cuda_runtime.h>
#include <cstdint>

// Problem constants
#define B_   32
#define K_   3
#define N_   512
#define FIN  64
#define FOUT 64
#define T_   64
#define R_   (K_ * N_)       // 1536  combined (k,m) reduction dim
#define C_   (FOUT * T_)     // 4096  combined (o,t) column dim

// Scratch
__device__ float g_A2[(size_t)B_ * N_ * R_];   // [b][n][k*512+m]
__device__ float g_Z2[(size_t)B_ * R_ * C_];   // [b][k*512+m][o*64+t]

// ---------------------------------------------------------------------------
// packed f32x2 helpers (kept for k_xtheta)
// ---------------------------------------------------------------------------
union U64 {
    unsigned long long u;
    float2 f;
};
__device__ __forceinline__ void fma2(unsigned long long& d,
                                     unsigned long long a,
                                     unsigned long long b) {
    asm("fma.rn.f32x2 %0, %1, %2, %3;" : "=l"(d) : "l"(a), "l"(b), "l"(d));
}

__device__ __forceinline__ uint32_t f2tf32(float f) {
    uint32_t r;
    asm("cvt.rna.tf32.f32 %0, %1;" : "=r"(r) : "f"(f));
    return r;
}

// ---------------------------------------------------------------------------
// Kernel 1: A2[b][n][k*512+m] = cheb * softmax (unchanged, ~60us)
// ---------------------------------------------------------------------------
__global__ void __launch_bounds__(128) k_softmax_aeff(
    const float* __restrict__ scores,
    const float* __restrict__ adj,
    const float* __restrict__ mask,
    const float* __restrict__ cheb)
{
    const int n = blockIdx.x, k = blockIdx.y, b = blockIdx.z;
    const int tid  = threadIdx.x;
    const int lane = tid & 31, wid = tid >> 5;

    const float4* srow = (const float4*)(scores + (((size_t)(b * K_ + k) * N_ + n) * N_));
    const float4* arow = (const float4*)(adj    + (size_t)n * N_);
    const float4* mrow = (const float4*)(mask   + ((size_t)(k * N_ + n) * N_));
    const float4* crow = (const float4*)(cheb   + ((size_t)(k * N_ + n) * N_));

    float4 s = srow[tid], a = arow[tid], mk = mrow[tid];
    float v0 = s.x + a.x * mk.x;
    float v1 = s.y + a.y * mk.y;
    float v2 = s.z + a.z * mk.z;
    float v3 = s.w + a.w * mk.w;

    float mx = fmaxf(fmaxf(v0, v1), fmaxf(v2, v3));
    #pragma unroll
    for (int o = 16; o; o >>= 1) mx = fmaxf(mx, __shfl_xor_sync(0xffffffffu, mx, o));
    __shared__ float rmax[4], rsum[4];
    if (lane == 0) rmax[wid] = mx;
    __syncthreads();
    mx = fmaxf(fmaxf(rmax[0], rmax[1]), fmaxf(rmax[2], rmax[3]));

    float e0 = __expf(v0 - mx);
    float e1 = __expf(v1 - mx);
    float e2 = __expf(v2 - mx);
    float e3 = __expf(v3 - mx);

    float sm = (e0 + e1) + (e2 + e3);
    #pragma unroll
    for (int o = 16; o; o >>= 1) sm += __shfl_xor_sync(0xffffffffu, sm, o);
    if (lane == 0) rsum[wid] = sm;
    __syncthreads();
    sm = (rsum[0] + rsum[1]) + (rsum[2] + rsum[3]);
    float inv = 1.0f / sm;

    float4 c = crow[tid];
    float4 o4;
    o4.x = c.x * (e0 * inv);
    o4.y = c.y * (e1 * inv);
    o4.z = c.z * (e2 * inv);
    o4.w = c.w * (e3 * inv);

    float4* dst = (float4*)(g_A2 + (((size_t)(b * N_ + n) * K_ + k) * N_));
    dst[tid] = o4;
}

// ---------------------------------------------------------------------------
// Kernel 2: z[b][k*512+m][o*64+t] = sum_i x[b,m,i,t]*Theta[k,i,o] (unchanged)
// ---------------------------------------------------------------------------
__global__ void __launch_bounds__(256) k_xtheta(
    const float* __restrict__ x,
    const float* __restrict__ Theta)
{
    const int m = blockIdx.x, k = blockIdx.y, b = blockIdx.z;
    const int tid = threadIdx.x;

    __shared__ float Xs[FIN * T_];
    __shared__ float Th[FIN * FOUT];

    const float4* xg = (const float4*)(x + ((size_t)(b * N_ + m) * (FIN * T_)));
    const float4* tg = (const float4*)(Theta + (size_t)k * FIN * FOUT);
    float4* Xs4 = (float4*)Xs;
    float4* Th4 = (float4*)Th;
    #pragma unroll
    for (int j = 0; j < 4; j++) {
        Xs4[tid + j * 256] = xg[tid + j * 256];
        Th4[tid + j * 256] = tg[tid + j * 256];
    }
    __syncthreads();

    const int tx = tid & 15;
    const int ty = tid >> 4;

    U64 acc[4][2];
    #pragma unroll
    for (int oj = 0; oj < 4; oj++) { acc[oj][0].u = 0ull; acc[oj][1].u = 0ull; }

    #pragma unroll 8
    for (int i = 0; i < FIN; i++) {
        float4 xv = Xs4[i * 16 + tx];
        float4 tv = Th4[i * 16 + ty];
        U64 xp0; xp0.f = make_float2(xv.x, xv.y);
        U64 xp1; xp1.f = make_float2(xv.z, xv.w);
        float to[4] = {tv.x, tv.y, tv.z, tv.w};
        #pragma unroll
        for (int oj = 0; oj < 4; oj++) {
            U64 ad; ad.f = make_float2(to[oj], to[oj]);
            fma2(acc[oj][0].u, ad.u, xp0.u);
            fma2(acc[oj][1].u, ad.u, xp1.u);
        }
    }

    float* zb = g_Z2 + ((size_t)(b * R_ + k * N_ + m) * C_);
    #pragma unroll
    for (int oj = 0; oj < 4; oj++) {
        float4 v;
        v.x = acc[oj][0].f.x; v.y = acc[oj][0].f.y;
        v.z = acc[oj][1].f.x; v.w = acc[oj][1].f.y;
        *(float4*)(zb + (ty * 4 + oj) * T_ + tx * 4) = v;
    }
}

// ---------------------------------------------------------------------------
// Kernel 3 (NEW): tensor-core tf32 GEMM.
// Per batch b: out[b] = relu(A2[b] (512x1536) @ Z2[b] (1536x4096))
// 128x128 tile, KT=16 double-buffered, 8 warps (2x4), warp tile 64x32,
// mma.sync.m16n8k8.tf32. Smem rows padded to 136 floats (conflict-free frags).
// ---------------------------------------------------------------------------
#define LDPAD 136
#define KTILE 16
#define NKT   (R_ / KTILE)   // 96

__device__ __forceinline__ void mma_tf32(float* c, const uint32_t* a, const uint32_t* bb) {
    asm volatile(
        "mma.sync.aligned.m16n8k8.row.col.f32.tf32.tf32.f32 "
        "{%0,%1,%2,%3}, {%4,%5,%6,%7}, {%8,%9}, {%0,%1,%2,%3};"
        : "+f"(c[0]), "+f"(c[1]), "+f"(c[2]), "+f"(c[3])
        : "r"(a[0]), "r"(a[1]), "r"(a[2]), "r"(a[3]), "r"(bb[0]), "r"(bb[1]));
}

__global__ void __launch_bounds__(256, 2) k_gemm_tc(float* __restrict__ out)
{
    const int nt = blockIdx.x, mt = blockIdx.y, b = blockIdx.z;
    __shared__ uint32_t sA[2][KTILE * LDPAD];
    __shared__ uint32_t sB[2][KTILE * LDPAD];

    const int tid  = threadIdx.x;
    const int lane = tid & 31, wid = tid >> 5;
    const int wm = (wid >> 2) * 64;      // warp m offset (0,64)
    const int wn = (wid & 3) * 32;       // warp n offset (0..96)

    // A loader: 128 rows x (2 half-rows of 8 k) ; B loader: 16 k-rows x 128 n
    const int arow = tid >> 1, akq = tid & 1;
    const int brow = tid >> 4, bcol = (tid & 15) * 8;

    const float* Ag = g_A2 + (size_t)b * N_ * R_ + (size_t)(mt * 128 + arow) * R_ + akq * 8;
    const float* Bg = g_Z2 + (size_t)b * R_ * C_ + (size_t)brow * C_ + (size_t)nt * 128 + bcol;

    float acc[4][4][4];
    #pragma unroll
    for (int mi = 0; mi < 4; mi++)
        #pragma unroll
        for (int ni = 0; ni < 4; ni++)
            #pragma unroll
            for (int j = 0; j < 4; j++) acc[mi][ni][j] = 0.f;

    // prologue: load tile 0
    float4 av0 = *(const float4*)(Ag);
    float4 av1 = *(const float4*)(Ag + 4);
    float4 bv0 = *(const float4*)(Bg);
    float4 bv1 = *(const float4*)(Bg + 4);
    {
        uint32_t* da = &sA[0][0];
        da[(akq * 8 + 0) * LDPAD + arow] = f2tf32(av0.x);
        da[(akq * 8 + 1) * LDPAD + arow] = f2tf32(av0.y);
        da[(akq * 8 + 2) * LDPAD + arow] = f2tf32(av0.z);
        da[(akq * 8 + 3) * LDPAD + arow] = f2tf32(av0.w);
        da[(akq * 8 + 4) * LDPAD + arow] = f2tf32(av1.x);
        da[(akq * 8 + 5) * LDPAD + arow] = f2tf32(av1.y);
        da[(akq * 8 + 6) * LDPAD + arow] = f2tf32(av1.z);
        da[(akq * 8 + 7) * LDPAD + arow] = f2tf32(av1.w);
        uint4 p0, p1;
        p0.x = f2tf32(bv0.x); p0.y = f2tf32(bv0.y); p0.z = f2tf32(bv0.z); p0.w = f2tf32(bv0.w);
        p1.x = f2tf32(bv1.x); p1.y = f2tf32(bv1.y); p1.z = f2tf32(bv1.z); p1.w = f2tf32(bv1.w);
        *(uint4*)&sB[0][brow * LDPAD + bcol]     = p0;
        *(uint4*)&sB[0][brow * LDPAD + bcol + 4] = p1;
    }
    __syncthreads();

    const int fr = lane >> 2;   // 0..7
    const int fc = lane & 3;    // 0..3

    for (int kt = 0; kt < NKT; kt++) {
        const int p = kt & 1;
        // prefetch next tile
        if (kt + 1 < NKT) {
            const float* Agn = Ag + (size_t)(kt + 1) * KTILE;
            const float* Bgn = Bg + (size_t)(kt + 1) * KTILE * C_;
            av0 = *(const float4*)(Agn);
            av1 = *(const float4*)(Agn + 4);
            bv0 = *(const float4*)(Bgn);
            bv1 = *(const float4*)(Bgn + 4);
        }

        // compute on buffer p
        const uint32_t* pa = &sA[p][0];
        const uint32_t* pb = &sB[p][0];
        #pragma unroll
        for (int kk = 0; kk < 2; kk++) {
            uint32_t afr[4][4], bfr[4][2];
            const int k0 = kk * 8 + fc;
            #pragma unroll
            for (int mi = 0; mi < 4; mi++) {
                const int m0 = wm + mi * 16 + fr;
                afr[mi][0] = pa[k0 * LDPAD + m0];
                afr[mi][1] = pa[k0 * LDPAD + m0 + 8];
                afr[mi][2] = pa[(k0 + 4) * LDPAD + m0];
                afr[mi][3] = pa[(k0 + 4) * LDPAD + m0 + 8];
            }
            #pragma unroll
            for (int ni = 0; ni < 4; ni++) {
                const int n0 = wn + ni * 8 + fr;
                bfr[ni][0] = pb[k0 * LDPAD + n0];
                bfr[ni][1] = pb[(k0 + 4) * LDPAD + n0];
            }
            #pragma unroll
            for (int mi = 0; mi < 4; mi++)
                #pragma unroll
                for (int ni = 0; ni < 4; ni++)
                    mma_tf32(acc[mi][ni], afr[mi], bfr[ni]);
        }

        // store next tile into the other buffer
        if (kt + 1 < NKT) {
            uint32_t* da = &sA[1 - p][0];
            da[(akq * 8 + 0) * LDPAD + arow] = f2tf32(av0.x);
            da[(akq * 8 + 1) * LDPAD + arow] = f2tf32(av0.y);
            da[(akq * 8 + 2) * LDPAD + arow] = f2tf32(av0.z);
            da[(akq * 8 + 3) * LDPAD + arow] = f2tf32(av0.w);
            da[(akq * 8 + 4) * LDPAD + arow] = f2tf32(av1.x);
            da[(akq * 8 + 5) * LDPAD + arow] = f2tf32(av1.y);
            da[(akq * 8 + 6) * LDPAD + arow] = f2tf32(av1.z);
            da[(akq * 8 + 7) * LDPAD + arow] = f2tf32(av1.w);
            uint4 p0, p1;
            p0.x = f2tf32(bv0.x); p0.y = f2tf32(bv0.y); p0.z = f2tf32(bv0.z); p0.w = f2tf32(bv0.w);
            p1.x = f2tf32(bv1.x); p1.y = f2tf32(bv1.y); p1.z = f2tf32(bv1.z); p1.w = f2tf32(bv1.w);
            *(uint4*)&sB[1 - p][brow * LDPAD + bcol]     = p0;
            *(uint4*)&sB[1 - p][brow * LDPAD + bcol + 4] = p1;
        }
        __syncthreads();
    }

    // epilogue: relu + store
    float* Cb = out + (size_t)b * N_ * C_ + (size_t)(mt * 128) * C_ + (size_t)nt * 128;
    #pragma unroll
    for (int mi = 0; mi < 4; mi++) {
        #pragma unroll
        for (int ni = 0; ni < 4; ni++) {
            const int r0 = wm + mi * 16 + fr;
            const int c0 = wn + ni * 8 + fc * 2;
            float2 v0, v1;
            v0.x = fmaxf(acc[mi][ni][0], 0.f);
            v0.y = fmaxf(acc[mi][ni][1], 0.f);
            v1.x = fmaxf(acc[mi][ni][2], 0.f);
            v1.y = fmaxf(acc[mi][ni][3], 0.f);
            *(float2*)(Cb + (size_t)r0 * C_ + c0)       = v0;
            *(float2*)(Cb + (size_t)(r0 + 8) * C_ + c0) = v1;
        }
    }
}

// ---------------------------------------------------------------------------
// Launch
// ---------------------------------------------------------------------------
extern "C" void kernel_launch(void* const* d_in, const int* in_sizes, int n_in,
                              void* d_out, int out_size) {
    (void)in_sizes; (void)n_in; (void)out_size;
    const float* x      = (const float*)d_in[0];  // [B,N,FIN,T]
    const float* scores = (const float*)d_in[1];  // [B,K,N,N]
    const float* adj    = (const float*)d_in[2];  // [N,N]
    const float* cheb   = (const float*)d_in[3];  // [K,N,N]
    const float* Theta  = (const float*)d_in[4];  // [K,FIN,FOUT]
    const float* mask   = (const float*)d_in[5];  // [K,N,N]
    float* out = (float*)d_out;                   // [B,N,FOUT,T]

    dim3 g1(N_, K_, B_);
    k_softmax_aeff<<<g1, 128>>>(scores, adj, mask, cheb);

    dim3 g2(N_, K_, B_);
    k_xtheta<<<g2, 256>>>(x, Theta);

    dim3 g3(C_ / 128, N_ / 128, B_);
    k_gemm_tc<<<g3, 256>>>(out);
}

// round 5
// speedup vs baseline: 3.4215x; 1.1457x over previous
#include <cuda_runtime.h>
#include <cstdint>

// Problem constants
#define B_   32
#define K_   3
#define N_   512
#define FIN  64
#define FOUT 64
#define T_   64
#define R_   (K_ * N_)       // 1536
#define C_   (FOUT * T_)     // 4096

__device__ float g_A2[(size_t)B_ * N_ * R_];   // [b][n][k*512+m], tf32-rounded
__device__ float g_Z2[(size_t)B_ * R_ * C_];   // [b][k*512+m][o*64+t], tf32-rounded

__device__ __forceinline__ uint32_t f2tf32(float f) {
    uint32_t r;
    asm("cvt.rna.tf32.f32 %0, %1;" : "=r"(r) : "f"(f));
    return r;
}
__device__ __forceinline__ uint32_t f2tf32_u(uint32_t f) {
    uint32_t r;
    asm("cvt.rna.tf32.f32 %0, %1;" : "=r"(r) : "f"(__uint_as_float(f)));
    return r;
}

__device__ __forceinline__ void cp16(uint32_t dst_smem, const void* src) {
    asm volatile("cp.async.cg.shared.global [%0], [%1], 16;\n" :: "r"(dst_smem), "l"(src));
}
__device__ __forceinline__ void cp_commit() { asm volatile("cp.async.commit_group;\n"); }
__device__ __forceinline__ void cp_wait0() { asm volatile("cp.async.wait_group 0;\n"); }
__device__ __forceinline__ void cp_wait1() { asm volatile("cp.async.wait_group 1;\n"); }

__device__ __forceinline__ void mma_tf32(float* c, const uint32_t* a, const uint32_t* bb) {
    asm volatile(
        "mma.sync.aligned.m16n8k8.row.col.f32.tf32.tf32.f32 "
        "{%0,%1,%2,%3}, {%4,%5,%6,%7}, {%8,%9}, {%0,%1,%2,%3};"
        : "+f"(c[0]), "+f"(c[1]), "+f"(c[2]), "+f"(c[3])
        : "r"(a[0]), "r"(a[1]), "r"(a[2]), "r"(a[3]), "r"(bb[0]), "r"(bb[1]));
}

// ---------------------------------------------------------------------------
// Kernel 1: A2 = cheb * softmax(...), output tf32-rounded
// ---------------------------------------------------------------------------
__global__ void __launch_bounds__(128) k_softmax_aeff(
    const float* __restrict__ scores,
    const float* __restrict__ adj,
    const float* __restrict__ mask,
    const float* __restrict__ cheb)
{
    const int n = blockIdx.x, k = blockIdx.y, b = blockIdx.z;
    const int tid  = threadIdx.x;
    const int lane = tid & 31, wid = tid >> 5;

    const float4* srow = (const float4*)(scores + (((size_t)(b * K_ + k) * N_ + n) * N_));
    const float4* arow = (const float4*)(adj    + (size_t)n * N_);
    const float4* mrow = (const float4*)(mask   + ((size_t)(k * N_ + n) * N_));
    const float4* crow = (const float4*)(cheb   + ((size_t)(k * N_ + n) * N_));

    float4 s = srow[tid], a = arow[tid], mk = mrow[tid];
    float v0 = s.x + a.x * mk.x;
    float v1 = s.y + a.y * mk.y;
    float v2 = s.z + a.z * mk.z;
    float v3 = s.w + a.w * mk.w;

    float mx = fmaxf(fmaxf(v0, v1), fmaxf(v2, v3));
    #pragma unroll
    for (int o = 16; o; o >>= 1) mx = fmaxf(mx, __shfl_xor_sync(0xffffffffu, mx, o));
    __shared__ float rmax[4], rsum[4];
    if (lane == 0) rmax[wid] = mx;
    __syncthreads();
    mx = fmaxf(fmaxf(rmax[0], rmax[1]), fmaxf(rmax[2], rmax[3]));

    float e0 = __expf(v0 - mx);
    float e1 = __expf(v1 - mx);
    float e2 = __expf(v2 - mx);
    float e3 = __expf(v3 - mx);

    float sm = (e0 + e1) + (e2 + e3);
    #pragma unroll
    for (int o = 16; o; o >>= 1) sm += __shfl_xor_sync(0xffffffffu, sm, o);
    if (lane == 0) rsum[wid] = sm;
    __syncthreads();
    sm = (rsum[0] + rsum[1]) + (rsum[2] + rsum[3]);
    float inv = 1.0f / sm;

    float4 c = crow[tid];
    float4 o4;
    o4.x = __uint_as_float(f2tf32(c.x * (e0 * inv)));
    o4.y = __uint_as_float(f2tf32(c.y * (e1 * inv)));
    o4.z = __uint_as_float(f2tf32(c.z * (e2 * inv)));
    o4.w = __uint_as_float(f2tf32(c.w * (e3 * inv)));

    float4* dst = (float4*)(g_A2 + (((size_t)(b * N_ + n) * K_ + k) * N_));
    dst[tid] = o4;
}

// ---------------------------------------------------------------------------
// Kernel 2 (NEW): z = x @ Theta on tensor cores.
// Block = (m-pair, b). GEMM rows=(m_local,t)=128, cols=o=64, red=i=64, looped
// over k=0..2 reusing one x load. 256 threads = 8 warps, warp tile 16x64.
// smem (u32 units): x[128][72] @0, Th[64][72] @9216, staging 8x[64][20] @13824.
// Total 24064 u32 = 96256 B -> 2 blocks/SM.
// ---------------------------------------------------------------------------
#define XT_SMEM_BYTES 96256

__global__ void __launch_bounds__(256, 2) k_xtheta_tc(
    const float* __restrict__ x,
    const float* __restrict__ Theta)
{
    extern __shared__ uint32_t sm[];
    const int mblk = blockIdx.x;   // 0..255 (pair of m)
    const int b    = blockIdx.y;
    const int tid  = threadIdx.x;
    const int lane = tid & 31, wid = tid >> 5;
    const int fr = lane >> 2, fc = lane & 3;

    const uint32_t sbase = (uint32_t)__cvta_generic_to_shared(sm);

    // async-load x: 128 rows (m_l,i) x 64 t  ->  smem rows stride 72
    const float* xg = x + ((size_t)(b * N_ + mblk * 2)) * (FIN * T_);
    #pragma unroll
    for (int j = 0; j < 8; j++) {
        int f = tid * 8 + j;
        int row = f >> 4, ch = f & 15;
        cp16(sbase + (uint32_t)(row * 72 + ch * 4) * 4, xg + row * 64 + ch * 4);
    }
    cp_commit();

    const int m_l = wid >> 2;          // 0..1
    const int t0  = (wid & 3) * 16;    // 0..48
    uint32_t* stg = sm + 13824 + wid * 1280;   // [64][20]

    for (int k = 0; k < K_; k++) {
        // async-load Theta_k: 64 rows (i) x 64 o -> stride 72
        const float* tg = Theta + (size_t)k * FIN * FOUT;
        #pragma unroll
        for (int j = 0; j < 4; j++) {
            int f = tid * 4 + j;
            int row = f >> 4, ch = f & 15;
            cp16(sbase + (uint32_t)(9216 + row * 72 + ch * 4) * 4, tg + row * 64 + ch * 4);
        }
        cp_commit();
        cp_wait0();
        __syncthreads();

        float acc[8][4];
        #pragma unroll
        for (int ni = 0; ni < 8; ni++)
            #pragma unroll
            for (int j = 0; j < 4; j++) acc[ni][j] = 0.f;

        #pragma unroll
        for (int ks = 0; ks < 8; ks++) {
            const int i0 = ks * 8 + fc;
            uint32_t afr[4];
            const int xrow = m_l * 64 + i0;
            afr[0] = f2tf32_u(sm[xrow * 72 + t0 + fr]);
            afr[1] = f2tf32_u(sm[xrow * 72 + t0 + fr + 8]);
            afr[2] = f2tf32_u(sm[(xrow + 4) * 72 + t0 + fr]);
            afr[3] = f2tf32_u(sm[(xrow + 4) * 72 + t0 + fr + 8]);
            #pragma unroll
            for (int ni = 0; ni < 8; ni++) {
                const int o0 = ni * 8 + fr;
                uint32_t bfr[2];
                bfr[0] = f2tf32_u(sm[9216 + i0 * 72 + o0]);
                bfr[1] = f2tf32_u(sm[9216 + (i0 + 4) * 72 + o0]);
                mma_tf32(acc[ni], afr, bfr);
            }
        }

        // stage transposed: staging[o][t_local], stride 20
        #pragma unroll
        for (int ni = 0; ni < 8; ni++) {
            const int o = ni * 8 + 2 * fc;
            stg[o * 20 + fr]            = f2tf32(acc[ni][0]);
            stg[(o + 1) * 20 + fr]      = f2tf32(acc[ni][1]);
            stg[o * 20 + fr + 8]        = f2tf32(acc[ni][2]);
            stg[(o + 1) * 20 + fr + 8]  = f2tf32(acc[ni][3]);
        }
        __syncwarp();

        // coalesced store: z[(k, m)][o*64 + t]
        float* zb = g_Z2 + ((size_t)(b * R_ + k * N_ + mblk * 2 + m_l)) * C_ + t0;
        #pragma unroll
        for (int p = 0; p < 8; p++) {
            const int o  = p * 8 + (lane >> 2);
            const int tq = lane & 3;
            float4 v = *(float4*)&stg[o * 20 + tq * 4];
            *(float4*)(zb + o * 64 + tq * 4) = v;
        }
        __syncthreads();   // protect Theta smem before next k's cp.async
    }
}

// ---------------------------------------------------------------------------
// Kernel 3 (NEW): out[b] = relu(A2[b] (512x1536) @ Z2[b] (1536x4096))
// Tile 256x128, 512 threads (16 warps 4x4, warp tile 64x32), 3-stage cp.async.
// Inputs pre-rounded to tf32 -> no cvt in hot loop.
// smem (u32): A stage s at s*5120: [256][20]; B stage s at 15360+s*2176: [16][136].
// Total 21888 u32 = 87552 B.
// ---------------------------------------------------------------------------
#define GM_SMEM_BYTES 87552
#define NKT 96

__global__ void __launch_bounds__(512, 1) k_gemm_tc(float* __restrict__ out)
{
    extern __shared__ uint32_t sm[];
    const int nt = blockIdx.x, mt = blockIdx.y, b = blockIdx.z;
    const int tid  = threadIdx.x;
    const int lane = tid & 31, wid = tid >> 5;
    const int fr = lane >> 2, fc = lane & 3;
    const int wm = (wid >> 2) * 64;
    const int wn = (wid & 3) * 32;

    const uint32_t sbase = (uint32_t)__cvta_generic_to_shared(sm);
    const float* Ag = g_A2 + (size_t)b * N_ * R_ + (size_t)(mt * 256) * R_;
    const float* Bg = g_Z2 + (size_t)b * R_ * C_ + nt * 128;

    // loader indices
    const int la_row = tid >> 1;            // wrong granularity; use flat below
    (void)la_row;
    const int lb_row = tid >> 5, lb_ch = tid & 31;

    auto load_stage = [&](int kt, int s) {
        #pragma unroll
        for (int j = 0; j < 2; j++) {
            int f = tid * 2 + j;
            int row = f >> 2, ch = f & 3;
            cp16(sbase + (uint32_t)(s * 5120 + row * 20 + ch * 4) * 4,
                 Ag + (size_t)row * R_ + kt * 16 + ch * 4);
        }
        cp16(sbase + (uint32_t)(15360 + s * 2176 + lb_row * 136 + lb_ch * 4) * 4,
             Bg + (size_t)(kt * 16 + lb_row) * C_ + lb_ch * 4);
        cp_commit();
    };

    load_stage(0, 0);
    load_stage(1, 1);

    float acc[4][4][4];
    #pragma unroll
    for (int mi = 0; mi < 4; mi++)
        #pragma unroll
        for (int ni = 0; ni < 4; ni++)
            #pragma unroll
            for (int j = 0; j < 4; j++) acc[mi][ni][j] = 0.f;

    for (int kt = 0; kt < NKT; kt++) {
        const int s = kt % 3;
        cp_wait1();
        __syncthreads();
        if (kt + 2 < NKT) load_stage(kt + 2, (kt + 2) % 3);

        const uint32_t* pa = sm + s * 5120;
        const uint32_t* pb = sm + 15360 + s * 2176;

        #pragma unroll
        for (int kk = 0; kk < 2; kk++) {
            const int k0 = kk * 8 + fc;
            uint32_t afr[4][4], bfr[4][2];
            #pragma unroll
            for (int mi = 0; mi < 4; mi++) {
                const int m0 = wm + mi * 16 + fr;
                afr[mi][0] = pa[m0 * 20 + k0];
                afr[mi][1] = pa[(m0 + 8) * 20 + k0];
                afr[mi][2] = pa[m0 * 20 + k0 + 4];
                afr[mi][3] = pa[(m0 + 8) * 20 + k0 + 4];
            }
            #pragma unroll
            for (int ni = 0; ni < 4; ni++) {
                const int n0 = wn + ni * 8 + fr;
                bfr[ni][0] = pb[k0 * 136 + n0];
                bfr[ni][1] = pb[(k0 + 4) * 136 + n0];
            }
            #pragma unroll
            for (int mi = 0; mi < 4; mi++)
                #pragma unroll
                for (int ni = 0; ni < 4; ni++)
                    mma_tf32(acc[mi][ni], afr[mi], bfr[ni]);
        }
        __syncthreads();
    }

    float* Cb = out + (size_t)b * N_ * C_ + (size_t)(mt * 256) * C_ + (size_t)nt * 128;
    #pragma unroll
    for (int mi = 0; mi < 4; mi++) {
        #pragma unroll
        for (int ni = 0; ni < 4; ni++) {
            const int r0 = wm + mi * 16 + fr;
            const int c0 = wn + ni * 8 + fc * 2;
            float2 v0, v1;
            v0.x = fmaxf(acc[mi][ni][0], 0.f);
            v0.y = fmaxf(acc[mi][ni][1], 0.f);
            v1.x = fmaxf(acc[mi][ni][2], 0.f);
            v1.y = fmaxf(acc[mi][ni][3], 0.f);
            *(float2*)(Cb + (size_t)r0 * C_ + c0)       = v0;
            *(float2*)(Cb + (size_t)(r0 + 8) * C_ + c0) = v1;
        }
    }
}

// ---------------------------------------------------------------------------
// Launch
// ---------------------------------------------------------------------------
extern "C" void kernel_launch(void* const* d_in, const int* in_sizes, int n_in,
                              void* d_out, int out_size) {
    (void)in_sizes; (void)n_in; (void)out_size;
    const float* x      = (const float*)d_in[0];
    const float* scores = (const float*)d_in[1];
    const float* adj    = (const float*)d_in[2];
    const float* cheb   = (const float*)d_in[3];
    const float* Theta  = (const float*)d_in[4];
    const float* mask   = (const float*)d_in[5];
    float* out = (float*)d_out;

    static int attr_done = 0;
    if (!attr_done) {
        cudaFuncSetAttribute(k_xtheta_tc, cudaFuncAttributeMaxDynamicSharedMemorySize, XT_SMEM_BYTES);
        cudaFuncSetAttribute(k_gemm_tc,  cudaFuncAttributeMaxDynamicSharedMemorySize, GM_SMEM_BYTES);
        attr_done = 1;
    }

    dim3 g1(N_, K_, B_);
    k_softmax_aeff<<<g1, 128>>>(scores, adj, mask, cheb);

    dim3 g2(N_ / 2, B_);
    k_xtheta_tc<<<g2, 256, XT_SMEM_BYTES>>>(x, Theta);

    dim3 g3(C_ / 128, N_ / 256, B_);
    k_gemm_tc<<<g3, 512, GM_SMEM_BYTES>>>(out);
}

// round 9
// speedup vs baseline: 4.5705x; 1.3358x over previous
#include <cuda_runtime.h>
#include <cstdint>

// Problem constants
#define B_   32
#define K_   3
#define N_   512
#define FIN  64
#define FOUT 64
#define T_   64
#define R_   (K_ * N_)       // 1536
#define C_   (FOUT * T_)     // 4096

__device__ float g_A2[(size_t)B_ * N_ * R_];   // [b][n][k*512+m], tf32-rounded
__device__ float g_Z2[(size_t)B_ * R_ * C_];   // [b][r][c], tf32-rounded

// ---------------------------------------------------------------------------
// helpers
// ---------------------------------------------------------------------------
__device__ __forceinline__ uint32_t f2tf32(float f) {
    uint32_t r;
    asm("cvt.rna.tf32.f32 %0, %1;" : "=r"(r) : "f"(f));
    return r;
}
__device__ __forceinline__ uint32_t f2tf32_u(uint32_t f) {
    uint32_t r;
    asm("cvt.rna.tf32.f32 %0, %1;" : "=r"(r) : "f"(__uint_as_float(f)));
    return r;
}
__device__ __forceinline__ void cp16(uint32_t dst_smem, const void* src) {
    asm volatile("cp.async.cg.shared.global [%0], [%1], 16;\n" :: "r"(dst_smem), "l"(src));
}
__device__ __forceinline__ void cp_commit() { asm volatile("cp.async.commit_group;\n"); }
__device__ __forceinline__ void cp_wait0() { asm volatile("cp.async.wait_group 0;\n"); }
__device__ __forceinline__ void cp_wait2() { asm volatile("cp.async.wait_group 2;\n"); }

__device__ __forceinline__ uint32_t smem_u32(const void* p) {
    uint32_t a;
    asm("{ .reg .u64 t; cvta.to.shared.u64 t, %1; cvt.u32.u64 %0, t; }" : "=r"(a) : "l"(p));
    return a;
}

__device__ __forceinline__ void mma_tf32(float* c, const uint32_t* a, const uint32_t* bb) {
    asm volatile(
        "mma.sync.aligned.m16n8k8.row.col.f32.tf32.tf32.f32 "
        "{%0,%1,%2,%3}, {%4,%5,%6,%7}, {%8,%9}, {%0,%1,%2,%3};"
        : "+f"(c[0]), "+f"(c[1]), "+f"(c[2]), "+f"(c[3])
        : "r"(a[0]), "r"(a[1]), "r"(a[2]), "r"(a[3]), "r"(bb[0]), "r"(bb[1]));
}
// ldmatrix on 32-bit data: 8x8 b16 matrix == 8x4 tf32; thread l -> [l>>2][l&3]
__device__ __forceinline__ void ldsm_x4(uint32_t* r, uint32_t a) {
    asm volatile("ldmatrix.sync.aligned.m8n8.x4.shared.b16 {%0,%1,%2,%3}, [%4];"
                 : "=r"(r[0]), "=r"(r[1]), "=r"(r[2]), "=r"(r[3]) : "r"(a));
}

// ---------------------------------------------------------------------------
// Kernel 1: A2 = cheb * softmax(scores + adj*mask), tf32-rounded (R5 verified)
// ---------------------------------------------------------------------------
__global__ void __launch_bounds__(128) k_softmax_aeff(
    const float* __restrict__ scores,
    const float* __restrict__ adj,
    const float* __restrict__ mask,
    const float* __restrict__ cheb)
{
    const int n = blockIdx.x, k = blockIdx.y, b = blockIdx.z;
    const int tid  = threadIdx.x;
    const int lane = tid & 31, wid = tid >> 5;

    const float4* srow = (const float4*)(scores + (((size_t)(b * K_ + k) * N_ + n) * N_));
    const float4* arow = (const float4*)(adj    + (size_t)n * N_);
    const float4* mrow = (const float4*)(mask   + ((size_t)(k * N_ + n) * N_));
    const float4* crow = (const float4*)(cheb   + ((size_t)(k * N_ + n) * N_));

    float4 s = srow[tid], a = arow[tid], mk = mrow[tid];
    float v0 = s.x + a.x * mk.x;
    float v1 = s.y + a.y * mk.y;
    float v2 = s.z + a.z * mk.z;
    float v3 = s.w + a.w * mk.w;

    float mx = fmaxf(fmaxf(v0, v1), fmaxf(v2, v3));
    #pragma unroll
    for (int o = 16; o; o >>= 1) mx = fmaxf(mx, __shfl_xor_sync(0xffffffffu, mx, o));
    __shared__ float rmax[4], rsum[4];
    if (lane == 0) rmax[wid] = mx;
    __syncthreads();
    mx = fmaxf(fmaxf(rmax[0], rmax[1]), fmaxf(rmax[2], rmax[3]));

    float e0 = __expf(v0 - mx);
    float e1 = __expf(v1 - mx);
    float e2 = __expf(v2 - mx);
    float e3 = __expf(v3 - mx);

    float sm = (e0 + e1) + (e2 + e3);
    #pragma unroll
    for (int o = 16; o; o >>= 1) sm += __shfl_xor_sync(0xffffffffu, sm, o);
    if (lane == 0) rsum[wid] = sm;
    __syncthreads();
    sm = (rsum[0] + rsum[1]) + (rsum[2] + rsum[3]);
    float inv = 1.0f / sm;

    float4 c = crow[tid];
    float4 o4;
    o4.x = __uint_as_float(f2tf32(c.x * (e0 * inv)));
    o4.y = __uint_as_float(f2tf32(c.y * (e1 * inv)));
    o4.z = __uint_as_float(f2tf32(c.z * (e2 * inv)));
    o4.w = __uint_as_float(f2tf32(c.w * (e3 * inv)));

    float4* dst = (float4*)(g_A2 + (((size_t)(b * N_ + n) * K_ + k) * N_));
    dst[tid] = o4;
}

// ---------------------------------------------------------------------------
// Kernel 2: z = x @ Theta (tf32 tensor cores, tf32-rounded out)  (R5 verified)
// ---------------------------------------------------------------------------
#define XT_SMEM_BYTES 96256

__global__ void __launch_bounds__(256, 2) k_xtheta_tc(
    const float* __restrict__ x,
    const float* __restrict__ Theta)
{
    extern __shared__ uint32_t sm[];
    const int mblk = blockIdx.x;
    const int b    = blockIdx.y;
    const int tid  = threadIdx.x;
    const int lane = tid & 31, wid = tid >> 5;
    const int fr = lane >> 2, fc = lane & 3;

    const uint32_t sbase = smem_u32(sm);

    const float* xg = x + ((size_t)(b * N_ + mblk * 2)) * (FIN * T_);
    #pragma unroll
    for (int j = 0; j < 8; j++) {
        int f = tid * 8 + j;
        int row = f >> 4, ch = f & 15;
        cp16(sbase + (uint32_t)(row * 72 + ch * 4) * 4, xg + row * 64 + ch * 4);
    }
    cp_commit();

    const int m_l = wid >> 2;
    const int t0  = (wid & 3) * 16;
    uint32_t* stg = sm + 13824 + wid * 1280;

    for (int k = 0; k < K_; k++) {
        const float* tg = Theta + (size_t)k * FIN * FOUT;
        #pragma unroll
        for (int j = 0; j < 4; j++) {
            int f = tid * 4 + j;
            int row = f >> 4, ch = f & 15;
            cp16(sbase + (uint32_t)(9216 + row * 72 + ch * 4) * 4, tg + row * 64 + ch * 4);
        }
        cp_commit();
        cp_wait0();
        __syncthreads();

        float acc[8][4];
        #pragma unroll
        for (int ni = 0; ni < 8; ni++)
            #pragma unroll
            for (int j = 0; j < 4; j++) acc[ni][j] = 0.f;

        #pragma unroll
        for (int ks = 0; ks < 8; ks++) {
            const int i0 = ks * 8 + fc;
            uint32_t afr[4];
            const int xrow = m_l * 64 + i0;
            afr[0] = f2tf32_u(sm[xrow * 72 + t0 + fr]);
            afr[1] = f2tf32_u(sm[xrow * 72 + t0 + fr + 8]);
            afr[2] = f2tf32_u(sm[(xrow + 4) * 72 + t0 + fr]);
            afr[3] = f2tf32_u(sm[(xrow + 4) * 72 + t0 + fr + 8]);
            #pragma unroll
            for (int ni = 0; ni < 8; ni++) {
                const int o0 = ni * 8 + fr;
                uint32_t bfr[2];
                bfr[0] = f2tf32_u(sm[9216 + i0 * 72 + o0]);
                bfr[1] = f2tf32_u(sm[9216 + (i0 + 4) * 72 + o0]);
                mma_tf32(acc[ni], afr, bfr);
            }
        }

        #pragma unroll
        for (int ni = 0; ni < 8; ni++) {
            const int o = ni * 8 + 2 * fc;
            stg[o * 20 + fr]            = f2tf32(acc[ni][0]);
            stg[(o + 1) * 20 + fr]      = f2tf32(acc[ni][1]);
            stg[o * 20 + fr + 8]        = f2tf32(acc[ni][2]);
            stg[(o + 1) * 20 + fr + 8]  = f2tf32(acc[ni][3]);
        }
        __syncwarp();

        float* zb = g_Z2 + ((size_t)(b * R_ + k * N_ + mblk * 2 + m_l)) * C_ + t0;
        #pragma unroll
        for (int p = 0; p < 8; p++) {
            const int o  = p * 8 + (lane >> 2);
            const int tq = lane & 3;
            float4 v = *(float4*)&stg[o * 20 + tq * 4];
            *(float4*)(zb + o * 64 + tq * 4) = v;
        }
        __syncthreads();
    }
}

// ---------------------------------------------------------------------------
// Kernel 3: out[b] = relu(A2[b] (512x1536) @ Z2[b] (1536x4096)), tf32 mma
// with LDSM A-fragments, 4-stage cp.async, 2 CTAs/SM.
// Tile 128x128, KT=16, 256 threads (8 warps 2x4), warp tile 64x32.
// Stage: A [128 rows][80 B] = 10240 B ; B [16 rows][544 B] = 8704 B.
// ---------------------------------------------------------------------------
#define ASTG   10240
#define BSTG   8704
#define STGB   (ASTG + BSTG)     // 18944
#define GM_SMEM_BYTES (4 * STGB) // 75776
#define NKT    96

__global__ void __launch_bounds__(256, 2) k_gemm_tf32(float* __restrict__ out)
{
    extern __shared__ uint8_t dynsm[];
    const int nt = blockIdx.x, mt = blockIdx.y, b = blockIdx.z;
    const int tid  = threadIdx.x;
    const int lane = tid & 31, wid = tid >> 5;
    const int wm = (wid >> 2) * 64;
    const int wn = (wid & 3) * 32;

    const uint32_t sbase = smem_u32(dynsm);

    const float* Ag = g_A2 + (size_t)b * N_ * R_ + (size_t)(mt * 128) * R_;
    const float* Bg = g_Z2 + (size_t)b * R_ * C_ + nt * 128;

    auto load_stage = [&](int kt, int s) {
        const uint32_t ab = sbase + s * STGB;
        const uint32_t bb = ab + ASTG;
        #pragma unroll
        for (int j = 0; j < 2; j++) {
            int q = j * 256 + tid;
            int row = q >> 2, c4 = q & 3;            // A: 128 rows x 4 chunks
            cp16(ab + row * 80 + c4 * 16, Ag + (size_t)row * R_ + kt * 16 + c4 * 4);
        }
        #pragma unroll
        for (int j = 0; j < 2; j++) {
            int q = j * 256 + tid;
            int row = q >> 5, c = q & 31;            // B: 16 rows x 32 chunks
            cp16(bb + row * 544 + c * 16, Bg + (size_t)(kt * 16 + row) * C_ + c * 4);
        }
        cp_commit();
    };

    load_stage(0, 0);
    load_stage(1, 1);
    load_stage(2, 2);

    float acc[4][4][4];
    #pragma unroll
    for (int mi = 0; mi < 4; mi++)
        #pragma unroll
        for (int ni = 0; ni < 4; ni++)
            #pragma unroll
            for (int j = 0; j < 4; j++) acc[mi][ni][j] = 0.f;

    const int lrow = lane & 15;      // LDSM row within m16
    const int lhi  = lane >> 4;      // LDSM k-half (4 tf32 = 16B)
    const int fr = lane >> 2, fc = lane & 3;

    for (int kt = 0; kt < NKT; kt++) {
        const int s = kt & 3;
        cp_wait2();
        __syncthreads();

        const uint32_t ab = sbase + s * STGB;
        const uint32_t* pb = (const uint32_t*)(dynsm + s * STGB + ASTG);

        #pragma unroll
        for (int kk = 0; kk < 2; kk++) {
            uint32_t afr[4][4], bfr[4][2];
            #pragma unroll
            for (int mi = 0; mi < 4; mi++) {
                ldsm_x4(afr[mi],
                        ab + (uint32_t)(wm + mi * 16 + lrow) * 80 + kk * 32 + lhi * 16);
            }
            #pragma unroll
            for (int ni = 0; ni < 4; ni++) {
                const int n0 = wn + ni * 8 + fr;
                bfr[ni][0] = pb[(kk * 8 + fc) * 136 + n0];
                bfr[ni][1] = pb[(kk * 8 + fc + 4) * 136 + n0];
            }
            #pragma unroll
            for (int mi = 0; mi < 4; mi++)
                #pragma unroll
                for (int ni = 0; ni < 4; ni++)
                    mma_tf32(acc[mi][ni], afr[mi], bfr[ni]);
        }

        if (kt + 3 < NKT) load_stage(kt + 3, (kt + 3) & 3);
    }

    // epilogue: relu + store fp32
    float* Cb = out + (size_t)b * N_ * C_ + (size_t)(mt * 128) * C_ + nt * 128;
    #pragma unroll
    for (int mi = 0; mi < 4; mi++) {
        #pragma unroll
        for (int ni = 0; ni < 4; ni++) {
            const int row = wm + mi * 16 + fr;
            const int col = wn + ni * 8 + fc * 2;
            float2 v0, v1;
            v0.x = fmaxf(acc[mi][ni][0], 0.f);
            v0.y = fmaxf(acc[mi][ni][1], 0.f);
            v1.x = fmaxf(acc[mi][ni][2], 0.f);
            v1.y = fmaxf(acc[mi][ni][3], 0.f);
            *(float2*)(Cb + (size_t)row * C_ + col)       = v0;
            *(float2*)(Cb + (size_t)(row + 8) * C_ + col) = v1;
        }
    }
}

// ---------------------------------------------------------------------------
// Launch
// ---------------------------------------------------------------------------
extern "C" void kernel_launch(void* const* d_in, const int* in_sizes, int n_in,
                              void* d_out, int out_size) {
    (void)in_sizes; (void)n_in; (void)out_size;
    const float* x      = (const float*)d_in[0];
    const float* scores = (const float*)d_in[1];
    const float* adj    = (const float*)d_in[2];
    const float* cheb   = (const float*)d_in[3];
    const float* Theta  = (const float*)d_in[4];
    const float* mask   = (const float*)d_in[5];
    float* out = (float*)d_out;

    static int attr_done = 0;
    if (!attr_done) {
        cudaFuncSetAttribute(k_xtheta_tc, cudaFuncAttributeMaxDynamicSharedMemorySize, XT_SMEM_BYTES);
        cudaFuncSetAttribute(k_gemm_tf32, cudaFuncAttributeMaxDynamicSharedMemorySize, GM_SMEM_BYTES);
        attr_done = 1;
    }

    dim3 g1(N_, K_, B_);
    k_softmax_aeff<<<g1, 128>>>(scores, adj, mask, cheb);

    dim3 g2(N_ / 2, B_);
    k_xtheta_tc<<<g2, 256, XT_SMEM_BYTES>>>(x, Theta);

    dim3 g3(C_ / 128, N_ / 128, B_);
    k_gemm_tf32<<<g3, 256, GM_SMEM_BYTES>>>(out);
}

// round 15
// speedup vs baseline: 4.9086x; 1.0740x over previous
#include <cuda_runtime.h>
#include <cstdint>

// Problem constants
#define B_   32
#define K_   3
#define N_   512
#define FIN  64
#define FOUT 64
#define T_   64
#define R_   (K_ * N_)       // 1536
#define C_   (FOUT * T_)     // 4096

__device__ float g_A2[(size_t)B_ * N_ * R_];   // [b][n][k*512+m], tf32-rounded
__device__ float g_Z2[(size_t)B_ * R_ * C_];   // [b][r][c], tf32-rounded

// ---------------------------------------------------------------------------
// helpers
// ---------------------------------------------------------------------------
__device__ __forceinline__ uint32_t f2tf32(float f) {
    uint32_t r;
    asm("cvt.rna.tf32.f32 %0, %1;" : "=r"(r) : "f"(f));
    return r;
}
__device__ __forceinline__ uint32_t f2tf32_u(uint32_t f) {
    uint32_t r;
    asm("cvt.rna.tf32.f32 %0, %1;" : "=r"(r) : "f"(__uint_as_float(f)));
    return r;
}
__device__ __forceinline__ void cp16(uint32_t dst_smem, const void* src) {
    asm volatile("cp.async.cg.shared.global [%0], [%1], 16;\n" :: "r"(dst_smem), "l"(src));
}
__device__ __forceinline__ void cp_commit() { asm volatile("cp.async.commit_group;\n"); }
__device__ __forceinline__ void cp_wait0() { asm volatile("cp.async.wait_group 0;\n"); }
__device__ __forceinline__ void cp_wait1() { asm volatile("cp.async.wait_group 1;\n"); }

__device__ __forceinline__ uint32_t smem_u32(const void* p) {
    uint32_t a;
    asm("{ .reg .u64 t; cvta.to.shared.u64 t, %1; cvt.u32.u64 %0, t; }" : "=r"(a) : "l"(p));
    return a;
}

__device__ __forceinline__ void mma_tf32(float* c, const uint32_t* a, const uint32_t* bb) {
    asm volatile(
        "mma.sync.aligned.m16n8k8.row.col.f32.tf32.tf32.f32 "
        "{%0,%1,%2,%3}, {%4,%5,%6,%7}, {%8,%9}, {%0,%1,%2,%3};"
        : "+f"(c[0]), "+f"(c[1]), "+f"(c[2]), "+f"(c[3])
        : "r"(a[0]), "r"(a[1]), "r"(a[2]), "r"(a[3]), "r"(bb[0]), "r"(bb[1]));
}
// ldmatrix on 32-bit data: 8x8 b16 matrix == 8x4 tf32; thread l -> [l>>2][l&3]
__device__ __forceinline__ void ldsm_x4(uint32_t* r, uint32_t a) {
    asm volatile("ldmatrix.sync.aligned.m8n8.x4.shared.b16 {%0,%1,%2,%3}, [%4];"
                 : "=r"(r[0]), "=r"(r[1]), "=r"(r[2]), "=r"(r[3]) : "r"(a));
}

// ---------------------------------------------------------------------------
// Kernel 1: A2 = cheb * softmax(scores + adj*mask), tf32-rounded (verified)
// ---------------------------------------------------------------------------
__global__ void __launch_bounds__(128) k_softmax_aeff(
    const float* __restrict__ scores,
    const float* __restrict__ adj,
    const float* __restrict__ mask,
    const float* __restrict__ cheb)
{
    const int n = blockIdx.x, k = blockIdx.y, b = blockIdx.z;
    const int tid  = threadIdx.x;
    const int lane = tid & 31, wid = tid >> 5;

    const float4* srow = (const float4*)(scores + (((size_t)(b * K_ + k) * N_ + n) * N_));
    const float4* arow = (const float4*)(adj    + (size_t)n * N_);
    const float4* mrow = (const float4*)(mask   + ((size_t)(k * N_ + n) * N_));
    const float4* crow = (const float4*)(cheb   + ((size_t)(k * N_ + n) * N_));

    float4 s = srow[tid], a = arow[tid], mk = mrow[tid];
    float v0 = s.x + a.x * mk.x;
    float v1 = s.y + a.y * mk.y;
    float v2 = s.z + a.z * mk.z;
    float v3 = s.w + a.w * mk.w;

    float mx = fmaxf(fmaxf(v0, v1), fmaxf(v2, v3));
    #pragma unroll
    for (int o = 16; o; o >>= 1) mx = fmaxf(mx, __shfl_xor_sync(0xffffffffu, mx, o));
    __shared__ float rmax[4], rsum[4];
    if (lane == 0) rmax[wid] = mx;
    __syncthreads();
    mx = fmaxf(fmaxf(rmax[0], rmax[1]), fmaxf(rmax[2], rmax[3]));

    float e0 = __expf(v0 - mx);
    float e1 = __expf(v1 - mx);
    float e2 = __expf(v2 - mx);
    float e3 = __expf(v3 - mx);

    float sm = (e0 + e1) + (e2 + e3);
    #pragma unroll
    for (int o = 16; o; o >>= 1) sm += __shfl_xor_sync(0xffffffffu, sm, o);
    if (lane == 0) rsum[wid] = sm;
    __syncthreads();
    sm = (rsum[0] + rsum[1]) + (rsum[2] + rsum[3]);
    float inv = 1.0f / sm;

    float4 c = crow[tid];
    float4 o4;
    o4.x = __uint_as_float(f2tf32(c.x * (e0 * inv)));
    o4.y = __uint_as_float(f2tf32(c.y * (e1 * inv)));
    o4.z = __uint_as_float(f2tf32(c.z * (e2 * inv)));
    o4.w = __uint_as_float(f2tf32(c.w * (e3 * inv)));

    float4* dst = (float4*)(g_A2 + (((size_t)(b * N_ + n) * K_ + k) * N_));
    dst[tid] = o4;
}

// ---------------------------------------------------------------------------
// Kernel 2: z = x @ Theta (tf32 tensor cores, tf32-rounded fp32 out) (R9)
// ---------------------------------------------------------------------------
#define XT_SMEM_BYTES 96256

__global__ void __launch_bounds__(256, 2) k_xtheta_tc(
    const float* __restrict__ x,
    const float* __restrict__ Theta)
{
    extern __shared__ uint32_t sm[];
    const int mblk = blockIdx.x;
    const int b    = blockIdx.y;
    const int tid  = threadIdx.x;
    const int lane = tid & 31, wid = tid >> 5;
    const int fr = lane >> 2, fc = lane & 3;

    const uint32_t sbase = smem_u32(sm);

    const float* xg = x + ((size_t)(b * N_ + mblk * 2)) * (FIN * T_);
    #pragma unroll
    for (int j = 0; j < 8; j++) {
        int f = tid * 8 + j;
        int row = f >> 4, ch = f & 15;
        cp16(sbase + (uint32_t)(row * 72 + ch * 4) * 4, xg + row * 64 + ch * 4);
    }
    cp_commit();

    const int m_l = wid >> 2;
    const int t0  = (wid & 3) * 16;
    uint32_t* stg = sm + 13824 + wid * 1280;

    for (int k = 0; k < K_; k++) {
        const float* tg = Theta + (size_t)k * FIN * FOUT;
        #pragma unroll
        for (int j = 0; j < 4; j++) {
            int f = tid * 4 + j;
            int row = f >> 4, ch = f & 15;
            cp16(sbase + (uint32_t)(9216 + row * 72 + ch * 4) * 4, tg + row * 64 + ch * 4);
        }
        cp_commit();
        cp_wait0();
        __syncthreads();

        float acc[8][4];
        #pragma unroll
        for (int ni = 0; ni < 8; ni++)
            #pragma unroll
            for (int j = 0; j < 4; j++) acc[ni][j] = 0.f;

        #pragma unroll
        for (int ks = 0; ks < 8; ks++) {
            const int i0 = ks * 8 + fc;
            uint32_t afr[4];
            const int xrow = m_l * 64 + i0;
            afr[0] = f2tf32_u(sm[xrow * 72 + t0 + fr]);
            afr[1] = f2tf32_u(sm[xrow * 72 + t0 + fr + 8]);
            afr[2] = f2tf32_u(sm[(xrow + 4) * 72 + t0 + fr]);
            afr[3] = f2tf32_u(sm[(xrow + 4) * 72 + t0 + fr + 8]);
            #pragma unroll
            for (int ni = 0; ni < 8; ni++) {
                const int o0 = ni * 8 + fr;
                uint32_t bfr[2];
                bfr[0] = f2tf32_u(sm[9216 + i0 * 72 + o0]);
                bfr[1] = f2tf32_u(sm[9216 + (i0 + 4) * 72 + o0]);
                mma_tf32(acc[ni], afr, bfr);
            }
        }

        #pragma unroll
        for (int ni = 0; ni < 8; ni++) {
            const int o = ni * 8 + 2 * fc;
            stg[o * 20 + fr]            = f2tf32(acc[ni][0]);
            stg[(o + 1) * 20 + fr]      = f2tf32(acc[ni][1]);
            stg[o * 20 + fr + 8]        = f2tf32(acc[ni][2]);
            stg[(o + 1) * 20 + fr + 8]  = f2tf32(acc[ni][3]);
        }
        __syncwarp();

        float* zb = g_Z2 + ((size_t)(b * R_ + k * N_ + mblk * 2 + m_l)) * C_ + t0;
        #pragma unroll
        for (int p = 0; p < 8; p++) {
            const int o  = p * 8 + (lane >> 2);
            const int tq = lane & 3;
            float4 v = *(float4*)&stg[o * 20 + tq * 4];
            *(float4*)(zb + o * 64 + tq * 4) = v;
        }
        __syncthreads();
    }
}

// ---------------------------------------------------------------------------
// Kernel 3: out[b] = relu(A2[b] (512x1536) @ Z2[b] (1536x4096)), tf32 mma.
// KT=32 (4 k8-steps), 3-stage cp.async ring, 2 CTAs/SM, 128x128 tile,
// 256 threads (8 warps 2x4), warp tile 64x32, A via LDSM.
// TAIL FIX: final iteration must wait_group 0 — no younger group exists to
// make wait_group 1 force completion of the last chunk's loads.
// Stage: A [128 rows][144 B] = 18432 ; B [32 rows][544 B] = 17408. x3 = 107520.
// ---------------------------------------------------------------------------
#define ASTG   18432
#define BSTG   17408
#define STGB   (ASTG + BSTG)     // 35840
#define GM_SMEM_BYTES (3 * STGB) // 107520
#define NKT    48                // R_/32

__global__ void __launch_bounds__(256, 2) k_gemm_tf32(float* __restrict__ out)
{
    extern __shared__ uint8_t dynsm[];
    const int nt = blockIdx.x, mt = blockIdx.y, b = blockIdx.z;
    const int tid  = threadIdx.x;
    const int lane = tid & 31, wid = tid >> 5;
    const int wm = (wid >> 2) * 64;
    const int wn = (wid & 3) * 32;

    const uint32_t sbase = smem_u32(dynsm);

    const float* Ag = g_A2 + (size_t)b * N_ * R_ + (size_t)(mt * 128) * R_;
    const float* Bg = g_Z2 + (size_t)b * R_ * C_ + nt * 128;

    auto load_stage = [&](int kt, int s) {
        const uint32_t ab = sbase + s * STGB;
        const uint32_t bb = ab + ASTG;
        #pragma unroll
        for (int j = 0; j < 4; j++) {
            int q = j * 256 + tid;
            int row = q >> 3, c8 = q & 7;            // A: 128 rows x 8 chunks of 16B
            cp16(ab + row * 144 + c8 * 16, Ag + (size_t)row * R_ + kt * 32 + c8 * 4);
        }
        #pragma unroll
        for (int j = 0; j < 4; j++) {
            int q = j * 256 + tid;
            int row = q >> 5, c = q & 31;            // B: 32 rows x 32 chunks of 16B
            cp16(bb + row * 544 + c * 16, Bg + (size_t)(kt * 32 + row) * C_ + c * 4);
        }
        cp_commit();
    };

    load_stage(0, 0);
    load_stage(1, 1);

    float acc[4][4][4];
    #pragma unroll
    for (int mi = 0; mi < 4; mi++)
        #pragma unroll
        for (int ni = 0; ni < 4; ni++)
            #pragma unroll
            for (int j = 0; j < 4; j++) acc[mi][ni][j] = 0.f;

    const int lrow = lane & 15;      // LDSM row within m16
    const int lhi  = lane >> 4;      // LDSM 16B-half select
    const int fr = lane >> 2, fc = lane & 3;

    for (int kt = 0; kt < NKT; kt++) {
        const int s = kt % 3;
        // Mid-loop: {g(kt), g(kt+1)} pending -> wait1 completes g(kt).
        // Last iteration: only g(NKT-1) pending -> wait1 would be a no-op
        // and race the final chunk's loads; must drain fully.
        if (kt < NKT - 1) cp_wait1(); else cp_wait0();
        __syncthreads();

        const uint32_t ab = sbase + s * STGB;
        const uint32_t* pb = (const uint32_t*)(dynsm + s * STGB + ASTG);

        #pragma unroll
        for (int kk = 0; kk < 4; kk++) {
            uint32_t afr[4][4], bfr[4][2];
            #pragma unroll
            for (int mi = 0; mi < 4; mi++) {
                ldsm_x4(afr[mi],
                        ab + (uint32_t)(wm + mi * 16 + lrow) * 144 + kk * 32 + lhi * 16);
            }
            #pragma unroll
            for (int ni = 0; ni < 4; ni++) {
                const int n0 = wn + ni * 8 + fr;
                bfr[ni][0] = pb[(kk * 8 + fc) * 136 + n0];
                bfr[ni][1] = pb[(kk * 8 + fc + 4) * 136 + n0];
            }
            #pragma unroll
            for (int mi = 0; mi < 4; mi++)
                #pragma unroll
                for (int ni = 0; ni < 4; ni++)
                    mma_tf32(acc[mi][ni], afr[mi], bfr[ni]);
        }

        if (kt + 2 < NKT) load_stage(kt + 2, (kt + 2) % 3);
    }

    // epilogue: relu + store fp32
    float* Cb = out + (size_t)b * N_ * C_ + (size_t)(mt * 128) * C_ + nt * 128;
    #pragma unroll
    for (int mi = 0; mi < 4; mi++) {
        #pragma unroll
        for (int ni = 0; ni < 4; ni++) {
            const int row = wm + mi * 16 + fr;
            const int col = wn + ni * 8 + fc * 2;
            float2 v0, v1;
            v0.x = fmaxf(acc[mi][ni][0], 0.f);
            v0.y = fmaxf(acc[mi][ni][1], 0.f);
            v1.x = fmaxf(acc[mi][ni][2], 0.f);
            v1.y = fmaxf(acc[mi][ni][3], 0.f);
            *(float2*)(Cb + (size_t)row * C_ + col)       = v0;
            *(float2*)(Cb + (size_t)(row + 8) * C_ + col) = v1;
        }
    }
}

// ---------------------------------------------------------------------------
// Launch
// ---------------------------------------------------------------------------
extern "C" void kernel_launch(void* const* d_in, const int* in_sizes, int n_in,
                              void* d_out, int out_size) {
    (void)in_sizes; (void)n_in; (void)out_size;
    const float* x      = (const float*)d_in[0];
    const float* scores = (const float*)d_in[1];
    const float* adj    = (const float*)d_in[2];
    const float* cheb   = (const float*)d_in[3];
    const float* Theta  = (const float*)d_in[4];
    const float* mask   = (const float*)d_in[5];
    float* out = (float*)d_out;

    static int attr_done = 0;
    if (!attr_done) {
        cudaFuncSetAttribute(k_xtheta_tc, cudaFuncAttributeMaxDynamicSharedMemorySize, XT_SMEM_BYTES);
        cudaFuncSetAttribute(k_gemm_tf32, cudaFuncAttributeMaxDynamicSharedMemorySize, GM_SMEM_BYTES);
        attr_done = 1;
    }

    dim3 g1(N_, K_, B_);
    k_softmax_aeff<<<g1, 128>>>(scores, adj, mask, cheb);

    dim3 g2(N_ / 2, B_);
    k_xtheta_tc<<<g2, 256, XT_SMEM_BYTES>>>(x, Theta);

    dim3 g3(C_ / 128, N_ / 128, B_);
    k_gemm_tf32<<<g3, 256, GM_SMEM_BYTES>>>(out);
}

// round 17
// speedup vs baseline: 7.4507x; 1.5179x over previous
#include <cuda_runtime.h>
#include <cuda_fp16.h>
#include <cstdint>

// Problem constants
#define B_   32
#define K_   3
#define N_   512
#define FIN  64
#define FOUT 64
#define T_   64
#define R_   (K_ * N_)       // 1536
#define C_   (FOUT * T_)     // 4096

#define A_SCALE     1024.0f
#define A_SCALE_INV (1.0f / 1024.0f)

// Scratch (fp16): A2h = A_eff * 1024, Z2h = z
__device__ __half g_A2h[(size_t)B_ * N_ * R_];   // [b][n][k*512+m]
__device__ __half g_Z2h[(size_t)B_ * R_ * C_];   // [b][r][c]

// ---------------------------------------------------------------------------
// helpers
// ---------------------------------------------------------------------------
__device__ __forceinline__ uint32_t f2tf32_u(uint32_t f) {
    uint32_t r;
    asm("cvt.rna.tf32.f32 %0, %1;" : "=r"(r) : "f"(__uint_as_float(f)));
    return r;
}
__device__ __forceinline__ void cp16(uint32_t dst_smem, const void* src) {
    asm volatile("cp.async.cg.shared.global [%0], [%1], 16;\n" :: "r"(dst_smem), "l"(src));
}
__device__ __forceinline__ void cp_commit() { asm volatile("cp.async.commit_group;\n"); }
__device__ __forceinline__ void cp_wait0() { asm volatile("cp.async.wait_group 0;\n"); }
__device__ __forceinline__ void cp_wait1() { asm volatile("cp.async.wait_group 1;\n"); }

__device__ __forceinline__ uint32_t smem_u32(const void* p) {
    uint32_t a;
    asm("{ .reg .u64 t; cvta.to.shared.u64 t, %1; cvt.u32.u64 %0, t; }" : "=r"(a) : "l"(p));
    return a;
}

// tf32 mma (k_xtheta)
__device__ __forceinline__ void mma_tf32(float* c, const uint32_t* a, const uint32_t* bb) {
    asm volatile(
        "mma.sync.aligned.m16n8k8.row.col.f32.tf32.tf32.f32 "
        "{%0,%1,%2,%3}, {%4,%5,%6,%7}, {%8,%9}, {%0,%1,%2,%3};"
        : "+f"(c[0]), "+f"(c[1]), "+f"(c[2]), "+f"(c[3])
        : "r"(a[0]), "r"(a[1]), "r"(a[2]), "r"(a[3]), "r"(bb[0]), "r"(bb[1]));
}
// fp16 mma + ldmatrix
__device__ __forceinline__ void mma_f16(float* c, const uint32_t* a, const uint32_t* b) {
    asm volatile(
        "mma.sync.aligned.m16n8k16.row.col.f32.f16.f16.f32 "
        "{%0,%1,%2,%3}, {%4,%5,%6,%7}, {%8,%9}, {%0,%1,%2,%3};"
        : "+f"(c[0]), "+f"(c[1]), "+f"(c[2]), "+f"(c[3])
        : "r"(a[0]), "r"(a[1]), "r"(a[2]), "r"(a[3]), "r"(b[0]), "r"(b[1]));
}
__device__ __forceinline__ void ldsm_x4(uint32_t* r, uint32_t a) {
    asm volatile("ldmatrix.sync.aligned.m8n8.x4.shared.b16 {%0,%1,%2,%3}, [%4];"
                 : "=r"(r[0]), "=r"(r[1]), "=r"(r[2]), "=r"(r[3]) : "r"(a));
}
__device__ __forceinline__ void ldsm_x4_t(uint32_t* r, uint32_t a) {
    asm volatile("ldmatrix.sync.aligned.m8n8.x4.trans.shared.b16 {%0,%1,%2,%3}, [%4];"
                 : "=r"(r[0]), "=r"(r[1]), "=r"(r[2]), "=r"(r[3]) : "r"(a));
}

// ---------------------------------------------------------------------------
// Kernel 1: A2h = 1024 * cheb * softmax(scores + adj*mask)   (fp16 out)
// ---------------------------------------------------------------------------
__global__ void __launch_bounds__(128) k_softmax_aeff(
    const float* __restrict__ scores,
    const float* __restrict__ adj,
    const float* __restrict__ mask,
    const float* __restrict__ cheb)
{
    const int n = blockIdx.x, k = blockIdx.y, b = blockIdx.z;
    const int tid  = threadIdx.x;
    const int lane = tid & 31, wid = tid >> 5;

    const float4* srow = (const float4*)(scores + (((size_t)(b * K_ + k) * N_ + n) * N_));
    const float4* arow = (const float4*)(adj    + (size_t)n * N_);
    const float4* mrow = (const float4*)(mask   + ((size_t)(k * N_ + n) * N_));
    const float4* crow = (const float4*)(cheb   + ((size_t)(k * N_ + n) * N_));

    float4 s = srow[tid], a = arow[tid], mk = mrow[tid];
    float v0 = s.x + a.x * mk.x;
    float v1 = s.y + a.y * mk.y;
    float v2 = s.z + a.z * mk.z;
    float v3 = s.w + a.w * mk.w;

    float mx = fmaxf(fmaxf(v0, v1), fmaxf(v2, v3));
    #pragma unroll
    for (int o = 16; o; o >>= 1) mx = fmaxf(mx, __shfl_xor_sync(0xffffffffu, mx, o));
    __shared__ float rmax[4], rsum[4];
    if (lane == 0) rmax[wid] = mx;
    __syncthreads();
    mx = fmaxf(fmaxf(rmax[0], rmax[1]), fmaxf(rmax[2], rmax[3]));

    float e0 = __expf(v0 - mx);
    float e1 = __expf(v1 - mx);
    float e2 = __expf(v2 - mx);
    float e3 = __expf(v3 - mx);

    float sm = (e0 + e1) + (e2 + e3);
    #pragma unroll
    for (int o = 16; o; o >>= 1) sm += __shfl_xor_sync(0xffffffffu, sm, o);
    if (lane == 0) rsum[wid] = sm;
    __syncthreads();
    sm = (rsum[0] + rsum[1]) + (rsum[2] + rsum[3]);
    float inv = A_SCALE / sm;

    float4 c = crow[tid];
    __half2 p0 = __floats2half2_rn(c.x * (e0 * inv), c.y * (e1 * inv));
    __half2 p1 = __floats2half2_rn(c.z * (e2 * inv), c.w * (e3 * inv));

    __half* dst = g_A2h + (((size_t)(b * N_ + n) * K_ + k) * N_) + tid * 4;
    union { __half2 h[2]; uint2 u; } pk;
    pk.h[0] = p0; pk.h[1] = p1;
    *(uint2*)dst = pk.u;
}

// ---------------------------------------------------------------------------
// Kernel 2: z = x @ Theta (tf32 tensor-core math, fp16 output)
// ---------------------------------------------------------------------------
#define XT_SMEM_BYTES 96256

__global__ void __launch_bounds__(256, 2) k_xtheta_tc(
    const float* __restrict__ x,
    const float* __restrict__ Theta)
{
    extern __shared__ uint32_t sm[];
    const int mblk = blockIdx.x;
    const int b    = blockIdx.y;
    const int tid  = threadIdx.x;
    const int lane = tid & 31, wid = tid >> 5;
    const int fr = lane >> 2, fc = lane & 3;

    const uint32_t sbase = smem_u32(sm);

    const float* xg = x + ((size_t)(b * N_ + mblk * 2)) * (FIN * T_);
    #pragma unroll
    for (int j = 0; j < 8; j++) {
        int f = tid * 8 + j;
        int row = f >> 4, ch = f & 15;
        cp16(sbase + (uint32_t)(row * 72 + ch * 4) * 4, xg + row * 64 + ch * 4);
    }
    cp_commit();

    const int m_l = wid >> 2;
    const int t0  = (wid & 3) * 16;
    __half* stg = (__half*)(sm + 13824 + wid * 768);   // [64][24] halves

    for (int k = 0; k < K_; k++) {
        const float* tg = Theta + (size_t)k * FIN * FOUT;
        #pragma unroll
        for (int j = 0; j < 4; j++) {
            int f = tid * 4 + j;
            int row = f >> 4, ch = f & 15;
            cp16(sbase + (uint32_t)(9216 + row * 72 + ch * 4) * 4, tg + row * 64 + ch * 4);
        }
        cp_commit();
        cp_wait0();
        __syncthreads();

        float acc[8][4];
        #pragma unroll
        for (int ni = 0; ni < 8; ni++)
            #pragma unroll
            for (int j = 0; j < 4; j++) acc[ni][j] = 0.f;

        #pragma unroll
        for (int ks = 0; ks < 8; ks++) {
            const int i0 = ks * 8 + fc;
            uint32_t afr[4];
            const int xrow = m_l * 64 + i0;
            afr[0] = f2tf32_u(sm[xrow * 72 + t0 + fr]);
            afr[1] = f2tf32_u(sm[xrow * 72 + t0 + fr + 8]);
            afr[2] = f2tf32_u(sm[(xrow + 4) * 72 + t0 + fr]);
            afr[3] = f2tf32_u(sm[(xrow + 4) * 72 + t0 + fr + 8]);
            #pragma unroll
            for (int ni = 0; ni < 8; ni++) {
                const int o0 = ni * 8 + fr;
                uint32_t bfr[2];
                bfr[0] = f2tf32_u(sm[9216 + i0 * 72 + o0]);
                bfr[1] = f2tf32_u(sm[9216 + (i0 + 4) * 72 + o0]);
                mma_tf32(acc[ni], afr, bfr);
            }
        }

        // stage (half) transposed: stg[o][t_local], stride 24 halves
        #pragma unroll
        for (int ni = 0; ni < 8; ni++) {
            const int o = ni * 8 + 2 * fc;
            stg[o * 24 + fr]           = __float2half_rn(acc[ni][0]);
            stg[(o + 1) * 24 + fr]     = __float2half_rn(acc[ni][1]);
            stg[o * 24 + fr + 8]       = __float2half_rn(acc[ni][2]);
            stg[(o + 1) * 24 + fr + 8] = __float2half_rn(acc[ni][3]);
        }
        __syncwarp();

        // coalesced fp16 store: z[(k,m)][o*64 + t], 16B chunks
        __half* zb = g_Z2h + ((size_t)(b * R_ + k * N_ + mblk * 2 + m_l)) * C_ + t0;
        #pragma unroll
        for (int p = 0; p < 4; p++) {
            const int o  = p * 16 + (lane >> 1);
            const int ch = lane & 1;
            *(uint4*)(zb + o * 64 + ch * 8) = *(uint4*)&stg[o * 24 + ch * 8];
        }
        __syncthreads();
    }
}

// ---------------------------------------------------------------------------
// Kernel 3: out[b] = relu(A2h[b] (512x1536) @ Z2h[b] (1536x4096)) / 1024
// fp16 m16n8k16 mma + ldmatrix. KT=32 (2 k16-steps), 3-stage cp.async ring,
// 2 CTAs/SM, 128x128 tile, 256 threads (8 warps 2x4), warp tile 64x32.
// TAIL FIX: final iteration drains with wait_group 0.
// Stage: A [128 rows][80 B] = 10240 ; B [32 rows][272 B] = 8704. x3 = 56832.
// ---------------------------------------------------------------------------
#define ASTG   10240
#define BSTG   8704
#define STGB   (ASTG + BSTG)     // 18944
#define GM_SMEM_BYTES (3 * STGB) // 56832
#define NKT    48                // R_/32

__global__ void __launch_bounds__(256, 2) k_gemm_f16(float* __restrict__ out)
{
    extern __shared__ uint8_t dynsm[];
    const int nt = blockIdx.x, mt = blockIdx.y, b = blockIdx.z;
    const int tid  = threadIdx.x;
    const int lane = tid & 31, wid = tid >> 5;
    const int wm = (wid >> 2) * 64;
    const int wn = (wid & 3) * 32;

    const uint32_t sbase = smem_u32(dynsm);

    const __half* Ag = g_A2h + (size_t)b * N_ * R_ + (size_t)(mt * 128) * R_;
    const __half* Bg = g_Z2h + (size_t)b * R_ * C_ + nt * 128;

    auto load_stage = [&](int kt, int s) {
        const uint32_t ab = sbase + s * STGB;
        const uint32_t bb = ab + ASTG;
        #pragma unroll
        for (int j = 0; j < 2; j++) {
            int q = j * 256 + tid;
            int row = q >> 2, c4 = q & 3;            // A: 128 rows x 4 chunks of 16B
            cp16(ab + row * 80 + c4 * 16, Ag + (size_t)row * R_ + kt * 32 + c4 * 8);
        }
        #pragma unroll
        for (int j = 0; j < 2; j++) {
            int q = j * 256 + tid;
            int row = q >> 4, c = q & 15;            // B: 32 rows x 16 chunks of 16B
            cp16(bb + row * 272 + c * 16, Bg + (size_t)(kt * 32 + row) * C_ + c * 8);
        }
        cp_commit();
    };

    load_stage(0, 0);
    load_stage(1, 1);

    float acc[4][4][4];
    #pragma unroll
    for (int mi = 0; mi < 4; mi++)
        #pragma unroll
        for (int ni = 0; ni < 4; ni++)
            #pragma unroll
            for (int j = 0; j < 4; j++) acc[mi][ni][j] = 0.f;

    const int lrow = lane & 15;      // LDSM row
    const int lhi  = lane >> 4;      // LDSM 16B-half / n8-half select
    const int fr = lane >> 2, fc = lane & 3;

    for (int kt = 0; kt < NKT; kt++) {
        const int s = kt % 3;
        // Mid-loop: {g(kt), g(kt+1)} pending -> wait1 completes g(kt).
        // Last iteration: only g(NKT-1) pending -> must drain fully (wait0).
        if (kt < NKT - 1) cp_wait1(); else cp_wait0();
        __syncthreads();

        const uint32_t ab = sbase + s * STGB;
        const uint32_t bb = ab + ASTG;

        #pragma unroll
        for (int kk = 0; kk < 2; kk++) {
            uint32_t afr[4][4], bfr[2][4];
            #pragma unroll
            for (int mi = 0; mi < 4; mi++) {
                ldsm_x4(afr[mi],
                        ab + (uint32_t)(wm + mi * 16 + lrow) * 80 + kk * 32 + lhi * 16);
            }
            #pragma unroll
            for (int nb = 0; nb < 2; nb++) {
                ldsm_x4_t(bfr[nb],
                          bb + (uint32_t)(kk * 16 + lrow) * 272
                             + (uint32_t)(wn + nb * 16 + lhi * 8) * 2);
            }
            #pragma unroll
            for (int mi = 0; mi < 4; mi++)
                #pragma unroll
                for (int ni = 0; ni < 4; ni++)
                    mma_f16(acc[mi][ni], afr[mi], &bfr[ni >> 1][(ni & 1) * 2]);
        }

        if (kt + 2 < NKT) load_stage(kt + 2, (kt + 2) % 3);
    }

    // epilogue: relu, unscale, store fp32
    float* Cb = out + (size_t)b * N_ * C_ + (size_t)(mt * 128) * C_ + nt * 128;
    #pragma unroll
    for (int mi = 0; mi < 4; mi++) {
        #pragma unroll
        for (int ni = 0; ni < 4; ni++) {
            const int row = wm + mi * 16 + fr;
            const int col = wn + ni * 8 + fc * 2;
            float2 v0, v1;
            v0.x = fmaxf(acc[mi][ni][0], 0.f) * A_SCALE_INV;
            v0.y = fmaxf(acc[mi][ni][1], 0.f) * A_SCALE_INV;
            v1.x = fmaxf(acc[mi][ni][2], 0.f) * A_SCALE_INV;
            v1.y = fmaxf(acc[mi][ni][3], 0.f) * A_SCALE_INV;
            *(float2*)(Cb + (size_t)row * C_ + col)       = v0;
            *(float2*)(Cb + (size_t)(row + 8) * C_ + col) = v1;
        }
    }
}

// ---------------------------------------------------------------------------
// Launch
// ---------------------------------------------------------------------------
extern "C" void kernel_launch(void* const* d_in, const int* in_sizes, int n_in,
                              void* d_out, int out_size) {
    (void)in_sizes; (void)n_in; (void)out_size;
    const float* x      = (const float*)d_in[0];
    const float* scores = (const float*)d_in[1];
    const float* adj    = (const float*)d_in[2];
    const float* cheb   = (const float*)d_in[3];
    const float* Theta  = (const float*)d_in[4];
    const float* mask   = (const float*)d_in[5];
    float* out = (float*)d_out;

    static int attr_done = 0;
    if (!attr_done) {
        cudaFuncSetAttribute(k_xtheta_tc, cudaFuncAttributeMaxDynamicSharedMemorySize, XT_SMEM_BYTES);
        cudaFuncSetAttribute(k_gemm_f16, cudaFuncAttributeMaxDynamicSharedMemorySize, GM_SMEM_BYTES);
        attr_done = 1;
    }

    dim3 g1(N_, K_, B_);
    k_softmax_aeff<<<g1, 128>>>(scores, adj, mask, cheb);

    dim3 g2(N_ / 2, B_);
    k_xtheta_tc<<<g2, 256, XT_SMEM_BYTES>>>(x, Theta);

    dim3 g3(C_ / 128, N_ / 128, B_);
    k_gemm_f16<<<g3, 256, GM_SMEM_BYTES>>>(out);
}